// round 5
// baseline (speedup 1.0000x reference)
#include <cuda_runtime.h>
#include <cuda_bf16.h>
#include <cstdint>
#include <cstddef>

#define B_SZ 16
#define T_SZ 4096
#define D_SZ 512
#define NTOK (B_SZ * T_SZ)     // 65536
#define NTOT 1536              // 3*U
#define BM 128
#define BN 128
#define BK 32
#define NCHUNK 32              // K=1024 / 32
#define NSTAGE 4
#define SA 36                  // A smem row stride (floats): [m][k], pad 4
#define SB 136                 // B smem row stride (floats): [k][n], pad 8
#define A_STAGE (BM * SA * 4)  // 18432 B
#define B_STAGE (BK * SB * 4)  // 17408 B
#define STG (A_STAGE + B_STAGE)          // 35840 B
#define DYN_SMEM (NSTAGE * STG)          // 143360 B
#define NC 64
#define LC 64

// ---------------- scratch ----------------
__device__ float g_act[(size_t)NTOK * NTOT];   // activated z|f|o
__device__ float g_Ac[B_SZ * NC * 512];
__device__ float g_Bc[B_SZ * NC * 512];
__device__ float g_Hs[B_SZ * NC * 512];

// ---------------- helpers ----------------
__device__ __forceinline__ uint32_t smem_u32(const void* p) {
    uint32_t a;
    asm("{ .reg .u64 t; cvta.to.shared.u64 t, %1; cvt.u32.u64 %0, t; }" : "=r"(a) : "l"(p));
    return a;
}
__device__ __forceinline__ uint32_t tf32(float x) {
    uint32_t r; asm("cvt.rna.tf32.f32 %0, %1;" : "=r"(r) : "f"(x)); return r;
}
__device__ __forceinline__ float sigm(float v) { return 1.0f / (1.0f + __expf(-v)); }

__device__ __forceinline__ void cp16(uint32_t dst, const void* src, uint32_t srcsize) {
    asm volatile("cp.async.cg.shared.global [%0], [%1], 16, %2;"
                 :: "r"(dst), "l"(src), "r"(srcsize) : "memory");
}
__device__ __forceinline__ void cp_commit() {
    asm volatile("cp.async.commit_group;" ::: "memory");
}
__device__ __forceinline__ void cp_wait2() {
    asm volatile("cp.async.wait_group 2;" ::: "memory");
}

__device__ __forceinline__ void mma_k8(float* c, const uint32_t* a, const uint32_t* b) {
    asm volatile(
        "mma.sync.aligned.m16n8k8.row.col.f32.tf32.tf32.f32 "
        "{%0,%1,%2,%3}, {%4,%5,%6,%7}, {%8,%9}, {%0,%1,%2,%3};"
        : "+f"(c[0]), "+f"(c[1]), "+f"(c[2]), "+f"(c[3])
        : "r"(a[0]), "r"(a[1]), "r"(a[2]), "r"(a[3]), "r"(b[0]), "r"(b[1]));
}

// ---------------- GEMM + activation ----------------
// Issue one K-chunk's cp.async loads into stage s.
__device__ __forceinline__ void issue_tile(
    char* smc, int stage, int kc, int m0,
    const float* __restrict__ x, const float* __restrict__ Wg, int ub, int tid)
{
    char* abuf = smc + stage * STG;
    char* bbuf = abuf + A_STAGE;
    int w  = (kc < 16) ? 0 : 1;
    int d0 = ((kc < 16) ? kc : (kc - 16)) * 32;
    // A: 128 rows (m) x 32 k, stored [m][k] stride SA
    #pragma unroll
    for (int i = 0; i < 4; i++) {
        int c = tid + i * 256;            // 0..1023
        int row = c >> 3, q = c & 7;      // q*4 = k offset
        int m = m0 + row;
        uint32_t ok = !(w == 0 && (m & (T_SZ - 1)) == 0);
        const float* src = ok ? (x + (size_t)(m - 1 + w) * D_SZ + d0 + q * 4) : x;
        uint32_t dst = smem_u32(abuf + (row * SA + q * 4) * 4);
        cp16(dst, src, ok ? 16u : 0u);
    }
    // B: 32 k x 128 n, stored [k][n] stride SB;  B[k][n] = Wg[(kbase+k)*512 + ub + n]
    int kbase = kc * 32;
    #pragma unroll
    for (int i = 0; i < 4; i++) {
        int c = tid + i * 256;
        int k = c >> 5, nq = c & 31;      // n = nq*4
        const float* src = Wg + (size_t)(kbase + k) * 512 + ub + nq * 4;
        uint32_t dst = smem_u32(bbuf + (k * SB + nq * 4) * 4);
        cp16(dst, src, 16u);
    }
}

__global__ void __launch_bounds__(256, 1) qrnn_gemm(
    const float* __restrict__ x,
    const float* __restrict__ Wz, const float* __restrict__ bz,
    const float* __restrict__ Wf, const float* __restrict__ bf,
    const float* __restrict__ Wo, const float* __restrict__ bo)
{
    extern __shared__ char smc[];
    int tid = threadIdx.x, wid = tid >> 5, lid = tid & 31;
    int g = lid >> 2, tg = lid & 3;
    int n0 = blockIdx.x * BN;
    int m0 = blockIdx.y * BM;
    int gate = n0 >> 9;
    const float* Wg = (gate == 0) ? Wz : (gate == 1) ? Wf : Wo;
    const float* bg = (gate == 0) ? bz : (gate == 1) ? bf : bo;
    int ub = n0 & 511;
    int mwa = (wid >> 1) * 32;   // warp m offset (4 warps)
    int nwa = (wid & 1) * 64;    // warp n offset (2 warps)

    float acc[2][8][4];
    #pragma unroll
    for (int mt = 0; mt < 2; mt++)
        #pragma unroll
        for (int nt = 0; nt < 8; nt++)
            #pragma unroll
            for (int r = 0; r < 4; r++) acc[mt][nt][r] = 0.f;

    // prologue: stages 0..2
    for (int s = 0; s < 3; s++) { issue_tile(smc, s, s, m0, x, Wg, ub, tid); cp_commit(); }

    for (int kc = 0; kc < NCHUNK; kc++) {
        cp_wait2();
        __syncthreads();
        const float* As = (const float*)(smc + (kc & 3) * STG);
        const float* Bs = (const float*)(smc + (kc & 3) * STG + A_STAGE);
        #pragma unroll
        for (int ks = 0; ks < 4; ks++) {
            int k0 = ks * 8 + tg;
            uint32_t a[2][4], b[8][2];
            #pragma unroll
            for (int mt = 0; mt < 2; mt++) {
                const float* ap  = As + (mwa + mt * 16 + g) * SA;
                const float* ap8 = ap + 8 * SA;
                a[mt][0] = tf32(ap[k0]);
                a[mt][1] = tf32(ap8[k0]);
                a[mt][2] = tf32(ap[k0 + 4]);
                a[mt][3] = tf32(ap8[k0 + 4]);
            }
            #pragma unroll
            for (int nt = 0; nt < 8; nt++) {
                const float* bp = Bs + k0 * SB + nwa + nt * 8 + g;
                b[nt][0] = tf32(bp[0]);
                b[nt][1] = tf32(bp[4 * SB]);
            }
            #pragma unroll
            for (int mt = 0; mt < 2; mt++)
                #pragma unroll
                for (int nt = 0; nt < 8; nt++)
                    mma_k8(acc[mt][nt], a[mt], b[nt]);
        }
        __syncthreads();
        if (kc + 3 < NCHUNK)
            issue_tile(smc, (kc + 3) & 3, kc + 3, m0, x, Wg, ub, tid);
        cp_commit();
    }

    // epilogue: bias + activation, write to g_act
    #pragma unroll
    for (int mt = 0; mt < 2; mt++) {
        int row = m0 + mwa + mt * 16 + g;
        #pragma unroll
        for (int nt = 0; nt < 8; nt++) {
            int col = nwa + nt * 8 + tg * 2;
            float b0 = bg[ub + col], b1 = bg[ub + col + 1];
            float t0 = acc[mt][nt][0] + b0, t1 = acc[mt][nt][1] + b1;
            float t2 = acc[mt][nt][2] + b0, t3 = acc[mt][nt][3] + b1;
            float2 v0, v1;
            if (gate == 0) { v0.x = tanhf(t0); v0.y = tanhf(t1); v1.x = tanhf(t2); v1.y = tanhf(t3); }
            else           { v0.x = sigm(t0);  v0.y = sigm(t1);  v1.x = sigm(t2);  v1.y = sigm(t3);  }
            *(float2*)(g_act + (size_t)row * NTOT + n0 + col) = v0;
            *(float2*)(g_act + (size_t)(row + 8) * NTOT + n0 + col) = v1;
        }
    }
}

// ---------------- scan ----------------
__global__ void __launch_bounds__(512) scan1() {
    int blk = blockIdx.x;              // b*NC + c
    int u = threadIdx.x;
    size_t base = (size_t)((blk >> 6) * T_SZ + (blk & 63) * LC) * NTOT;
    float A = 1.f, h = 0.f;
    for (int t = 0; t < LC; t++) {
        float f = g_act[base + (size_t)t * NTOT + 512 + u];
        float z = g_act[base + (size_t)t * NTOT + u];
        h = f * h + (1.f - f) * z;
        A *= f;
    }
    g_Ac[blk * 512 + u] = A;
    g_Bc[blk * 512 + u] = h;
}

__global__ void __launch_bounds__(512) scan2() {
    int b = blockIdx.x, u = threadIdx.x;
    float h = 0.f;
    for (int c = 0; c < NC; c++) {
        int i = (b * NC + c) * 512 + u;
        g_Hs[i] = h;
        h = g_Ac[i] * h + g_Bc[i];
    }
}

__global__ void __launch_bounds__(512) scan3(float* __restrict__ out) {
    int blk = blockIdx.x;
    int u = threadIdx.x;
    size_t base = (size_t)((blk >> 6) * T_SZ + (blk & 63) * LC) * NTOT;
    size_t ob = (size_t)((blk >> 6) * T_SZ + (blk & 63) * LC) * 512;
    float h = g_Hs[blk * 512 + u];
    for (int t = 0; t < LC; t++) {
        float z = g_act[base + (size_t)t * NTOT + u];
        float f = g_act[base + (size_t)t * NTOT + 512 + u];
        float o = g_act[base + (size_t)t * NTOT + 1024 + u];
        h = f * h + (1.f - f) * z;
        out[ob + (size_t)t * 512 + u] = o * h;
    }
}

// ---------------- launch ----------------
extern "C" void kernel_launch(void* const* d_in, const int* in_sizes, int n_in,
                              void* d_out, int out_size) {
    (void)in_sizes; (void)n_in; (void)out_size;
    const float* x  = (const float*)d_in[0];
    const float* Wz = (const float*)d_in[1];
    const float* bz = (const float*)d_in[2];
    const float* Wf = (const float*)d_in[3];
    const float* bf = (const float*)d_in[4];
    const float* Wo = (const float*)d_in[5];
    const float* bo = (const float*)d_in[6];
    float* out = (float*)d_out;

    static bool attr_done = false;
    if (!attr_done) {
        cudaFuncSetAttribute(qrnn_gemm, cudaFuncAttributeMaxDynamicSharedMemorySize, DYN_SMEM);
        attr_done = true;
    }
    dim3 grid(NTOT / BN, NTOK / BM);   // (12, 512)
    qrnn_gemm<<<grid, 256, DYN_SMEM>>>(x, Wz, bz, Wf, bf, Wo, bo);
    scan1<<<B_SZ * NC, 512>>>();
    scan2<<<B_SZ, 512>>>();
    scan3<<<B_SZ * NC, 512>>>(out);
}

// round 6
// speedup vs baseline: 1.7985x; 1.7985x over previous
#include <cuda_runtime.h>
#include <cuda_bf16.h>
#include <cstdint>
#include <cstddef>

#define B_SZ 16
#define T_SZ 4096
#define D_SZ 512
#define NTOK (B_SZ * T_SZ)     // 65536
#define NTOT 1536              // 3*U
#define KTOT 1024
#define BM 128
#define BN 128
#define BK 32
#define NCHUNK 32              // K=1024 / 32
#define SA 40                  // smem row stride in floats (A and B), bank-safe
#define A_STAGE (BM * SA * 4)  // 20480 B
#define B_STAGE (BN * SA * 4)  // 20480 B
#define STG (A_STAGE + B_STAGE)          // 40960 B
#define DYN_SMEM (2 * STG)               // 81920 B
#define NC 64
#define LC 64

// ---------------- scratch ----------------
__device__ float g_xr[(size_t)NTOK * D_SZ];    // x rounded + k-permuted (134 MB)
__device__ float g_wt[(size_t)NTOT * KTOT];    // W^T rounded + k-permuted (6.3 MB)
__device__ float g_act[(size_t)NTOK * NTOT];   // activated z|f|o (402 MB)
__device__ float g_Ac[B_SZ * NC * 512];
__device__ float g_Bc[B_SZ * NC * 512];
__device__ float g_Hs[B_SZ * NC * 512];

// ---------------- helpers ----------------
__device__ __forceinline__ uint32_t smem_u32(const void* p) {
    uint32_t a;
    asm("{ .reg .u64 t; cvta.to.shared.u64 t, %1; cvt.u32.u64 %0, t; }" : "=r"(a) : "l"(p));
    return a;
}
__device__ __forceinline__ float rna(float x) {
    float r; asm("cvt.rna.tf32.f32 %0, %1;" : "=f"(r) : "f"(x)); return r;
}
__device__ __forceinline__ float sigm(float v) { return 1.0f / (1.0f + __expf(-v)); }

__device__ __forceinline__ void cp16(uint32_t dst, const void* src, uint32_t srcsize) {
    asm volatile("cp.async.cg.shared.global [%0], [%1], 16, %2;"
                 :: "r"(dst), "l"(src), "r"(srcsize) : "memory");
}
__device__ __forceinline__ void cp_commit() {
    asm volatile("cp.async.commit_group;" ::: "memory");
}
__device__ __forceinline__ void cp_wait1() {
    asm volatile("cp.async.wait_group 1;" ::: "memory");
}

__device__ __forceinline__ void mma_k8(float* c, const uint32_t* a, const uint32_t* b) {
    asm volatile(
        "mma.sync.aligned.m16n8k8.row.col.f32.tf32.tf32.f32 "
        "{%0,%1,%2,%3}, {%4,%5,%6,%7}, {%8,%9}, {%0,%1,%2,%3};"
        : "+f"(c[0]), "+f"(c[1]), "+f"(c[2]), "+f"(c[3])
        : "r"(a[0]), "r"(a[1]), "r"(a[2]), "r"(a[3]), "r"(b[0]), "r"(b[1]));
}

// ---------------- prep: x -> rounded + permuted (within each 8: j -> (0,4,1,5,2,6,3,7) src order) ----------------
__global__ void __launch_bounds__(256) prep_x(const float* __restrict__ x) {
    size_t i = (size_t)blockIdx.x * blockDim.x + threadIdx.x;   // one 8-float group
    size_t base = i * 8;
    float4 a = *(const float4*)(x + base);
    float4 b = *(const float4*)(x + base + 4);
    float4 o0 = make_float4(rna(a.x), rna(b.x), rna(a.y), rna(b.y));
    float4 o1 = make_float4(rna(a.z), rna(b.z), rna(a.w), rna(b.w));
    *(float4*)(g_xr + base)     = o0;
    *(float4*)(g_xr + base + 4) = o1;
}

// ---------------- prep: W[k][u] -> g_wt[n][kperm], rounded ----------------
__device__ __forceinline__ int perm8(int t) {
    int j = t & 7;
    return (t & ~7) | ((j < 4) ? (2 * j) : (2 * (j - 4) + 1));
}
__global__ void __launch_bounds__(256) prep_w(
    const float* __restrict__ Wz, const float* __restrict__ Wf, const float* __restrict__ Wo)
{
    __shared__ float tile[32][33];
    int gate = blockIdx.z;
    const float* Wg = (gate == 0) ? Wz : (gate == 1) ? Wf : Wo;
    int kt = blockIdx.x * 32;   // k tile
    int ut = blockIdx.y * 32;   // u tile
    int tx = threadIdx.x, ty = threadIdx.y;   // 32 x 8
    #pragma unroll
    for (int j = 0; j < 4; j++) {
        int kr = ty + j * 8;
        tile[kr][tx] = Wg[(size_t)(kt + kr) * 512 + ut + tx];   // coalesced in u
    }
    __syncthreads();
    #pragma unroll
    for (int j = 0; j < 4; j++) {
        int ur = ty + j * 8;
        size_t n = (size_t)gate * 512 + ut + ur;
        g_wt[n * KTOT + kt + perm8(tx)] = rna(tile[tx][ur]);
    }
}

// ---------------- GEMM + activation ----------------
__device__ __forceinline__ void issue_tile(
    char* smc, int stage, int kc, int m0, int n0, int tid)
{
    char* abuf = smc + stage * STG;
    char* bbuf = abuf + A_STAGE;
    int w  = (kc < 16) ? 0 : 1;
    int d0 = ((kc < 16) ? kc : (kc - 16)) * 32;
    #pragma unroll
    for (int i = 0; i < 4; i++) {
        int c = tid + i * 256;            // 0..1023
        int row = c >> 3, q = c & 7;
        int m = m0 + row;
        uint32_t ok = !(w == 0 && (m & (T_SZ - 1)) == 0);
        const float* src = ok ? (g_xr + (size_t)(m - 1 + w) * D_SZ + d0 + q * 4) : g_xr;
        cp16(smem_u32(abuf + (row * SA + q * 4) * 4), src, ok ? 16u : 0u);
    }
    int kbase = kc * 32;
    #pragma unroll
    for (int i = 0; i < 4; i++) {
        int c = tid + i * 256;
        int row = c >> 3, q = c & 7;      // row = n local
        const float* src = g_wt + (size_t)(n0 + row) * KTOT + kbase + q * 4;
        cp16(smem_u32(bbuf + (row * SA + q * 4) * 4), src, 16u);
    }
}

__global__ void __launch_bounds__(256, 2) qrnn_gemm(
    const float* __restrict__ bz, const float* __restrict__ bf, const float* __restrict__ bo)
{
    extern __shared__ char smc[];
    int tid = threadIdx.x, wid = tid >> 5, lid = tid & 31;
    int g = lid >> 2, tg = lid & 3;
    int n0 = blockIdx.x * BN;
    int m0 = blockIdx.y * BM;
    int gate = n0 >> 9;
    const float* bg = (gate == 0) ? bz : (gate == 1) ? bf : bo;
    int ub = n0 & 511;
    int mwa = (wid >> 1) * 32;   // 4 warp rows
    int nwa = (wid & 1) * 64;    // 2 warp cols

    float acc[2][8][4];
    #pragma unroll
    for (int mt = 0; mt < 2; mt++)
        #pragma unroll
        for (int nt = 0; nt < 8; nt++)
            #pragma unroll
            for (int r = 0; r < 4; r++) acc[mt][nt][r] = 0.f;

    issue_tile(smc, 0, 0, m0, n0, tid); cp_commit();
    issue_tile(smc, 1, 1, m0, n0, tid); cp_commit();

    for (int kc = 0; kc < NCHUNK; kc++) {
        cp_wait1();
        __syncthreads();
        const float* As = (const float*)(smc + (kc & 1) * STG);
        const float* Bs = (const float*)(smc + (kc & 1) * STG + A_STAGE);
        #pragma unroll
        for (int ks = 0; ks < 4; ks++) {
            int ko = ks * 8 + 2 * tg;     // permuted: pair = (k0, k0+4)
            uint32_t a[2][4], b[8][2];
            #pragma unroll
            for (int mt = 0; mt < 2; mt++) {
                uint2 lo = *(const uint2*)(As + (mwa + mt * 16 + g) * SA + ko);
                uint2 hi = *(const uint2*)(As + (mwa + mt * 16 + g + 8) * SA + ko);
                a[mt][0] = lo.x; a[mt][2] = lo.y;
                a[mt][1] = hi.x; a[mt][3] = hi.y;
            }
            #pragma unroll
            for (int nt = 0; nt < 8; nt++) {
                uint2 v = *(const uint2*)(Bs + (nwa + nt * 8 + g) * SA + ko);
                b[nt][0] = v.x; b[nt][1] = v.y;
            }
            #pragma unroll
            for (int mt = 0; mt < 2; mt++)
                #pragma unroll
                for (int nt = 0; nt < 8; nt++)
                    mma_k8(acc[mt][nt], a[mt], b[nt]);
        }
        __syncthreads();
        if (kc + 2 < NCHUNK) issue_tile(smc, kc & 1, kc + 2, m0, n0, tid);
        cp_commit();
    }

    // epilogue: bias + activation -> g_act
    #pragma unroll
    for (int mt = 0; mt < 2; mt++) {
        int row = m0 + mwa + mt * 16 + g;
        #pragma unroll
        for (int nt = 0; nt < 8; nt++) {
            int col = nwa + nt * 8 + tg * 2;
            float b0 = bg[ub + col], b1 = bg[ub + col + 1];
            float t0 = acc[mt][nt][0] + b0, t1 = acc[mt][nt][1] + b1;
            float t2 = acc[mt][nt][2] + b0, t3 = acc[mt][nt][3] + b1;
            float2 v0, v1;
            if (gate == 0) { v0.x = tanhf(t0); v0.y = tanhf(t1); v1.x = tanhf(t2); v1.y = tanhf(t3); }
            else           { v0.x = sigm(t0);  v0.y = sigm(t1);  v1.x = sigm(t2);  v1.y = sigm(t3);  }
            *(float2*)(g_act + (size_t)row * NTOT + n0 + col) = v0;
            *(float2*)(g_act + (size_t)(row + 8) * NTOT + n0 + col) = v1;
        }
    }
}

// ---------------- scan ----------------
__global__ void __launch_bounds__(512) scan1() {
    int blk = blockIdx.x;
    int u = threadIdx.x;
    size_t base = (size_t)((blk >> 6) * T_SZ + (blk & 63) * LC) * NTOT;
    float A = 1.f, h = 0.f;
    for (int t = 0; t < LC; t++) {
        float f = g_act[base + (size_t)t * NTOT + 512 + u];
        float z = g_act[base + (size_t)t * NTOT + u];
        h = f * h + (1.f - f) * z;
        A *= f;
    }
    g_Ac[blk * 512 + u] = A;
    g_Bc[blk * 512 + u] = h;
}

__global__ void __launch_bounds__(512) scan2() {
    int b = blockIdx.x, u = threadIdx.x;
    float h = 0.f;
    for (int c = 0; c < NC; c++) {
        int i = (b * NC + c) * 512 + u;
        g_Hs[i] = h;
        h = g_Ac[i] * h + g_Bc[i];
    }
}

__global__ void __launch_bounds__(512) scan3(float* __restrict__ out) {
    int blk = blockIdx.x;
    int u = threadIdx.x;
    size_t base = (size_t)((blk >> 6) * T_SZ + (blk & 63) * LC) * NTOT;
    size_t ob = (size_t)((blk >> 6) * T_SZ + (blk & 63) * LC) * 512;
    float h = g_Hs[blk * 512 + u];
    for (int t = 0; t < LC; t++) {
        float z = g_act[base + (size_t)t * NTOT + u];
        float f = g_act[base + (size_t)t * NTOT + 512 + u];
        float o = g_act[base + (size_t)t * NTOT + 1024 + u];
        h = f * h + (1.f - f) * z;
        out[ob + (size_t)t * 512 + u] = o * h;
    }
}

// ---------------- launch ----------------
extern "C" void kernel_launch(void* const* d_in, const int* in_sizes, int n_in,
                              void* d_out, int out_size) {
    (void)in_sizes; (void)n_in; (void)out_size;
    const float* x  = (const float*)d_in[0];
    const float* Wz = (const float*)d_in[1];
    const float* bz = (const float*)d_in[2];
    const float* Wf = (const float*)d_in[3];
    const float* bf = (const float*)d_in[4];
    const float* Wo = (const float*)d_in[5];
    const float* bo = (const float*)d_in[6];
    float* out = (float*)d_out;

    static bool attr_done = false;
    if (!attr_done) {
        cudaFuncSetAttribute(qrnn_gemm, cudaFuncAttributeMaxDynamicSharedMemorySize, DYN_SMEM);
        attr_done = true;
    }
    prep_x<<<(NTOK * D_SZ / 8 + 255) / 256, 256>>>(x);
    prep_w<<<dim3(KTOT / 32, 512 / 32, 3), dim3(32, 8)>>>(Wz, Wf, Wo);
    dim3 grid(NTOT / BN, NTOK / BM);   // (12, 512)
    qrnn_gemm<<<grid, 256, DYN_SMEM>>>(bz, bf, bo);
    scan1<<<B_SZ * NC, 512>>>();
    scan2<<<B_SZ, 512>>>();
    scan3<<<B_SZ * NC, 512>>>(out);
}

// round 7
// speedup vs baseline: 1.9194x; 1.0672x over previous
#include <cuda_runtime.h>
#include <cuda_bf16.h>
#include <cstdint>
#include <cstddef>

#define B_SZ 16
#define T_SZ 4096
#define D_SZ 512
#define NTOK (B_SZ * T_SZ)     // 65536
#define NTOT 1536              // 3*U
#define KTOT 1024
#define BM 128
#define BN 128
#define BK 32
#define NCHUNK 32              // K=1024 / 32
#define SA 40                  // smem row stride in floats, bank-safe
#define A_STAGE (BM * SA * 4)  // 20480 B
#define B_STAGE (BN * SA * 4)  // 20480 B
#define STG (A_STAGE + B_STAGE)          // 40960 B
#define DYN_SMEM (2 * STG)               // 81920 B
#define NC 64
#define LC 64

// ---------------- scratch ----------------
__device__ float g_xr[(size_t)NTOK * D_SZ];    // x rounded + k-permuted
__device__ float g_wt[(size_t)NTOT * KTOT];    // W^T rounded + k-permuted
__device__ float g_act[(size_t)NTOK * NTOT];   // activated z|f|o
__device__ float g_Ac[B_SZ * NC * 512];
__device__ float g_Bc[B_SZ * NC * 512];
__device__ float g_Hs[B_SZ * NC * 512];

// ---------------- helpers ----------------
__device__ __forceinline__ uint32_t smem_u32(const void* p) {
    uint32_t a;
    asm("{ .reg .u64 t; cvta.to.shared.u64 t, %1; cvt.u32.u64 %0, t; }" : "=r"(a) : "l"(p));
    return a;
}
__device__ __forceinline__ float rna(float x) {
    float r; asm("cvt.rna.tf32.f32 %0, %1;" : "=f"(r) : "f"(x)); return r;
}
__device__ __forceinline__ float sigm(float v) { return 1.0f / (1.0f + __expf(-v)); }

__device__ __forceinline__ void cp16(uint32_t dst, const void* src, uint32_t srcsize) {
    asm volatile("cp.async.cg.shared.global [%0], [%1], 16, %2;"
                 :: "r"(dst), "l"(src), "r"(srcsize) : "memory");
}
__device__ __forceinline__ void cp_commit() {
    asm volatile("cp.async.commit_group;" ::: "memory");
}
__device__ __forceinline__ void cp_wait1() {
    asm volatile("cp.async.wait_group 1;" ::: "memory");
}

__device__ __forceinline__ void mma_k8(float* c, const uint32_t* a, const uint32_t* b) {
    asm volatile(
        "mma.sync.aligned.m16n8k8.row.col.f32.tf32.tf32.f32 "
        "{%0,%1,%2,%3}, {%4,%5,%6,%7}, {%8,%9}, {%0,%1,%2,%3};"
        : "+f"(c[0]), "+f"(c[1]), "+f"(c[2]), "+f"(c[3])
        : "r"(a[0]), "r"(a[1]), "r"(a[2]), "r"(a[3]), "r"(b[0]), "r"(b[1]));
}

// ---------------- prep: x -> rounded + permuted (within each 8: dst order (0,4,1,5,2,6,3,7)) ----------------
__global__ void __launch_bounds__(256) prep_x(const float* __restrict__ x) {
    size_t i = (size_t)blockIdx.x * blockDim.x + threadIdx.x;
    size_t base = i * 8;
    float4 a = *(const float4*)(x + base);
    float4 b = *(const float4*)(x + base + 4);
    float4 o0 = make_float4(rna(a.x), rna(b.x), rna(a.y), rna(b.y));
    float4 o1 = make_float4(rna(a.z), rna(b.z), rna(a.w), rna(b.w));
    *(float4*)(g_xr + base)     = o0;
    *(float4*)(g_xr + base + 4) = o1;
}

// ---------------- prep: W[k][u] -> g_wt[n][kperm], rounded ----------------
__device__ __forceinline__ int perm8(int t) {
    int j = t & 7;
    return (t & ~7) | ((j < 4) ? (2 * j) : (2 * (j - 4) + 1));
}
__global__ void __launch_bounds__(256) prep_w(
    const float* __restrict__ Wz, const float* __restrict__ Wf, const float* __restrict__ Wo)
{
    __shared__ float tile[32][33];
    int gate = blockIdx.z;
    const float* Wg = (gate == 0) ? Wz : (gate == 1) ? Wf : Wo;
    int kt = blockIdx.x * 32;
    int ut = blockIdx.y * 32;
    int tx = threadIdx.x, ty = threadIdx.y;   // 32 x 8
    #pragma unroll
    for (int j = 0; j < 4; j++) {
        int kr = ty + j * 8;
        tile[kr][tx] = Wg[(size_t)(kt + kr) * 512 + ut + tx];
    }
    __syncthreads();
    #pragma unroll
    for (int j = 0; j < 4; j++) {
        int ur = ty + j * 8;
        size_t n = (size_t)gate * 512 + ut + ur;
        g_wt[n * KTOT + kt + perm8(tx)] = rna(tile[tx][ur]);
    }
}

// ---------------- GEMM + activation ----------------
__device__ __forceinline__ void issue_tile(
    char* smc, int stage, int kc, int m0, int n0, int tid)
{
    char* abuf = smc + stage * STG;
    char* bbuf = abuf + A_STAGE;
    int w  = (kc < 16) ? 0 : 1;
    int d0 = ((kc < 16) ? kc : (kc - 16)) * 32;
    #pragma unroll
    for (int i = 0; i < 8; i++) {
        int c = tid + i * 128;            // 0..1023
        int row = c >> 3, q = c & 7;
        int m = m0 + row;
        uint32_t ok = !(w == 0 && (m & (T_SZ - 1)) == 0);
        const float* src = ok ? (g_xr + (size_t)(m - 1 + w) * D_SZ + d0 + q * 4) : g_xr;
        cp16(smem_u32(abuf + (row * SA + q * 4) * 4), src, ok ? 16u : 0u);
    }
    int kbase = kc * 32;
    #pragma unroll
    for (int i = 0; i < 8; i++) {
        int c = tid + i * 128;
        int row = c >> 3, q = c & 7;      // row = n local
        const float* src = g_wt + (size_t)(n0 + row) * KTOT + kbase + q * 4;
        cp16(smem_u32(bbuf + (row * SA + q * 4) * 4), src, 16u);
    }
}

__global__ void __launch_bounds__(128, 2) qrnn_gemm(
    const float* __restrict__ bz, const float* __restrict__ bf, const float* __restrict__ bo)
{
    extern __shared__ char smc[];
    int tid = threadIdx.x, wid = tid >> 5, lid = tid & 31;
    int g = lid >> 2, tg = lid & 3;
    int n0 = blockIdx.x * BN;
    int m0 = blockIdx.y * BM;
    int gate = n0 >> 9;
    const float* bg = (gate == 0) ? bz : (gate == 1) ? bf : bo;
    int ub = n0 & 511;
    int mwa = (wid >> 1) * 64;   // 2 warp rows, 64 each
    int nwa = (wid & 1) * 64;    // 2 warp cols, 64 each

    float acc[4][8][4];
    #pragma unroll
    for (int mt = 0; mt < 4; mt++)
        #pragma unroll
        for (int nt = 0; nt < 8; nt++)
            #pragma unroll
            for (int r = 0; r < 4; r++) acc[mt][nt][r] = 0.f;

    issue_tile(smc, 0, 0, m0, n0, tid); cp_commit();
    issue_tile(smc, 1, 1, m0, n0, tid); cp_commit();

    for (int kc = 0; kc < NCHUNK; kc++) {
        cp_wait1();
        __syncthreads();
        const float* As = (const float*)(smc + (kc & 1) * STG);
        const float* Bs = (const float*)(smc + (kc & 1) * STG + A_STAGE);
        #pragma unroll
        for (int ks = 0; ks < 4; ks++) {
            int ko = ks * 8 + 2 * tg;     // perm8: pair = (k, k+4) adjacent
            uint32_t a[4][4], b[8][2];
            #pragma unroll
            for (int mt = 0; mt < 4; mt++) {
                uint2 lo = *(const uint2*)(As + (mwa + mt * 16 + g) * SA + ko);
                uint2 hi = *(const uint2*)(As + (mwa + mt * 16 + g + 8) * SA + ko);
                a[mt][0] = lo.x; a[mt][2] = lo.y;
                a[mt][1] = hi.x; a[mt][3] = hi.y;
            }
            #pragma unroll
            for (int nt = 0; nt < 8; nt++) {
                uint2 v = *(const uint2*)(Bs + (nwa + nt * 8 + g) * SA + ko);
                b[nt][0] = v.x; b[nt][1] = v.y;
            }
            #pragma unroll
            for (int mt = 0; mt < 4; mt++)
                #pragma unroll
                for (int nt = 0; nt < 8; nt++)
                    mma_k8(acc[mt][nt], a[mt], b[nt]);
        }
        __syncthreads();
        if (kc + 2 < NCHUNK) issue_tile(smc, kc & 1, kc + 2, m0, n0, tid);
        cp_commit();
    }

    // epilogue: bias + activation -> g_act
    #pragma unroll
    for (int mt = 0; mt < 4; mt++) {
        int row = m0 + mwa + mt * 16 + g;
        #pragma unroll
        for (int nt = 0; nt < 8; nt++) {
            int col = nwa + nt * 8 + tg * 2;
            float b0 = bg[ub + col], b1 = bg[ub + col + 1];
            float t0 = acc[mt][nt][0] + b0, t1 = acc[mt][nt][1] + b1;
            float t2 = acc[mt][nt][2] + b0, t3 = acc[mt][nt][3] + b1;
            float2 v0, v1;
            if (gate == 0) { v0.x = tanhf(t0); v0.y = tanhf(t1); v1.x = tanhf(t2); v1.y = tanhf(t3); }
            else           { v0.x = sigm(t0);  v0.y = sigm(t1);  v1.x = sigm(t2);  v1.y = sigm(t3);  }
            *(float2*)(g_act + (size_t)row * NTOT + n0 + col) = v0;
            *(float2*)(g_act + (size_t)(row + 8) * NTOT + n0 + col) = v1;
        }
    }
}

// ---------------- scan ----------------
__global__ void __launch_bounds__(512) scan1() {
    int blk = blockIdx.x;
    int u = threadIdx.x;
    size_t base = (size_t)((blk >> 6) * T_SZ + (blk & 63) * LC) * NTOT;
    float A = 1.f, h = 0.f;
    for (int t = 0; t < LC; t++) {
        float f = g_act[base + (size_t)t * NTOT + 512 + u];
        float z = g_act[base + (size_t)t * NTOT + u];
        h = f * h + (1.f - f) * z;
        A *= f;
    }
    g_Ac[blk * 512 + u] = A;
    g_Bc[blk * 512 + u] = h;
}

__global__ void __launch_bounds__(512) scan2() {
    int b = blockIdx.x, u = threadIdx.x;
    float h = 0.f;
    for (int c = 0; c < NC; c++) {
        int i = (b * NC + c) * 512 + u;
        g_Hs[i] = h;
        h = g_Ac[i] * h + g_Bc[i];
    }
}

__global__ void __launch_bounds__(512) scan3(float* __restrict__ out) {
    int blk = blockIdx.x;
    int u = threadIdx.x;
    size_t base = (size_t)((blk >> 6) * T_SZ + (blk & 63) * LC) * NTOT;
    size_t ob = (size_t)((blk >> 6) * T_SZ + (blk & 63) * LC) * 512;
    float h = g_Hs[blk * 512 + u];
    for (int t = 0; t < LC; t++) {
        float z = g_act[base + (size_t)t * NTOT + u];
        float f = g_act[base + (size_t)t * NTOT + 512 + u];
        float o = g_act[base + (size_t)t * NTOT + 1024 + u];
        h = f * h + (1.f - f) * z;
        out[ob + (size_t)t * 512 + u] = o * h;
    }
}

// ---------------- launch ----------------
extern "C" void kernel_launch(void* const* d_in, const int* in_sizes, int n_in,
                              void* d_out, int out_size) {
    (void)in_sizes; (void)n_in; (void)out_size;
    const float* x  = (const float*)d_in[0];
    const float* Wz = (const float*)d_in[1];
    const float* bz = (const float*)d_in[2];
    const float* Wf = (const float*)d_in[3];
    const float* bf = (const float*)d_in[4];
    const float* Wo = (const float*)d_in[5];
    const float* bo = (const float*)d_in[6];
    float* out = (float*)d_out;

    static bool attr_done = false;
    if (!attr_done) {
        cudaFuncSetAttribute(qrnn_gemm, cudaFuncAttributeMaxDynamicSharedMemorySize, DYN_SMEM);
        attr_done = true;
    }
    prep_x<<<(NTOK * D_SZ / 8 + 255) / 256, 256>>>(x);
    prep_w<<<dim3(KTOT / 32, 512 / 32, 3), dim3(32, 8)>>>(Wz, Wf, Wo);
    dim3 grid(NTOT / BN, NTOK / BM);   // (12, 512)
    qrnn_gemm<<<grid, 128, DYN_SMEM>>>(bz, bf, bo);
    scan1<<<B_SZ * NC, 512>>>();
    scan2<<<B_SZ, 512>>>();
    scan3<<<B_SZ * NC, 512>>>(out);
}